// round 4
// baseline (speedup 1.0000x reference)
#include <cuda_runtime.h>

// Causal depthwise conv1d (K=4) + SiLU, fp32.
// y[b,t,c] = silu( bias[c] + sum_k w[c,k] * x[b, t-3+k, c] )
//
// R4: register-double-buffered pipeline. Each thread owns one float4 channel
// group over a SEG=32 time segment, processed in NCHUNK=4 chunks of CH=8:
// loads of chunk j+1 are issued before computing chunk j, so ~8 LDG.128 are
// in flight continuously. Read amplification (SEG+3)/SEG = 1.094.

constexpr int CH     = 8;            // rows per chunk
constexpr int NCHUNK = 4;            // chunks per segment
constexpr int SEG    = CH * NCHUNK;  // 32 time steps per block
constexpr int TPB    = 256;

__device__ __forceinline__ float silu(float v) {
    return v / (1.0f + __expf(-v));
}

__device__ __forceinline__ void store_cs(float4* p, float4 v) {
    asm volatile("st.global.cs.v4.f32 [%0], {%1,%2,%3,%4};"
                 :: "l"(p), "f"(v.x), "f"(v.y), "f"(v.z), "f"(v.w) : "memory");
}

__global__ __launch_bounds__(TPB)
void shortconv1d_kernel(const float* __restrict__ x,
                        const float* __restrict__ w,
                        const float* __restrict__ bias,
                        float* __restrict__ y,
                        int T, int C) {
    const int Cd4 = C >> 2;
    const int c4  = blockIdx.x * TPB + threadIdx.x;
    if (c4 >= Cd4) return;
    const int c   = c4 << 2;
    const int b   = blockIdx.z;
    const int t0  = blockIdx.y * SEG;

    const float4* __restrict__ xp =
        reinterpret_cast<const float4*>(x) + ((size_t)b * T + t0) * Cd4 + c4;
    float4* __restrict__ yp =
        reinterpret_cast<float4*>(y) + ((size_t)b * T + t0) * Cd4 + c4;
    const size_t rs = (size_t)Cd4;   // float4 stride between time rows

    // Weights: row per channel is one contiguous float4. Bias: one float4.
    const float4* __restrict__ w4 = reinterpret_cast<const float4*>(w);
    const float4 wl0 = w4[c + 0];
    const float4 wl1 = w4[c + 1];
    const float4 wl2 = w4[c + 2];
    const float4 wl3 = w4[c + 3];
    const float4 bi  = reinterpret_cast<const float4*>(bias)[c4];

    // History p0..p2 = x[t-3..t-1]; zero-filled only for the first segment.
    float4 p0, p1, p2;
    {
        const float4 z = make_float4(0.f, 0.f, 0.f, 0.f);
        p0 = (t0 >= 3) ? xp[-3 * (ptrdiff_t)rs] : z;
        p1 = (t0 >= 3) ? xp[-2 * (ptrdiff_t)rs] : z;
        p2 = (t0 >= 3) ? xp[-1 * (ptrdiff_t)rs] : z;
    }

    float4 bufA[CH], bufB[CH];

    // Prologue: load chunk 0.
#pragma unroll
    for (int i = 0; i < CH; ++i) bufA[i] = xp[(size_t)i * rs];

#pragma unroll
    for (int j = 0; j < NCHUNK; ++j) {
        float4* cur = (j & 1) ? bufB : bufA;
        float4* nxt = (j & 1) ? bufA : bufB;

        // Prefetch chunk j+1 (stays within this segment).
        if (j < NCHUNK - 1) {
#pragma unroll
            for (int i = 0; i < CH; ++i)
                nxt[i] = xp[(size_t)((j + 1) * CH + i) * rs];
        }

        // Compute + store chunk j while prefetch is in flight.
#pragma unroll
        for (int r = 0; r < CH; ++r) {
            const float4 cv = cur[r];
            float4 acc;
            acc.x = fmaf(wl0.x, p0.x, fmaf(wl0.y, p1.x, fmaf(wl0.z, p2.x, fmaf(wl0.w, cv.x, bi.x))));
            acc.y = fmaf(wl1.x, p0.y, fmaf(wl1.y, p1.y, fmaf(wl1.z, p2.y, fmaf(wl1.w, cv.y, bi.y))));
            acc.z = fmaf(wl2.x, p0.z, fmaf(wl2.y, p1.z, fmaf(wl2.z, p2.z, fmaf(wl2.w, cv.z, bi.z))));
            acc.w = fmaf(wl3.x, p0.w, fmaf(wl3.y, p1.w, fmaf(wl3.z, p2.w, fmaf(wl3.w, cv.w, bi.w))));

            float4 out;
            out.x = silu(acc.x);
            out.y = silu(acc.y);
            out.z = silu(acc.z);
            out.w = silu(acc.w);

            store_cs(&yp[(size_t)(j * CH + r) * rs], out);

            p0 = p1; p1 = p2; p2 = cv;
        }
    }
}

extern "C" void kernel_launch(void* const* d_in, const int* in_sizes, int n_in,
                              void* d_out, int out_size) {
    const float* x    = (const float*)d_in[0];
    const float* w    = (const float*)d_in[1];
    const float* bias = (const float*)d_in[2];
    float* y          = (float*)d_out;

    const int C  = in_sizes[2];       // bias: (C,)
    const int BT = in_sizes[0] / C;   // B*T
    const int T  = 4096;
    const int B  = BT / T;

    dim3 block(TPB);
    dim3 grid((C / 4 + TPB - 1) / TPB, T / SEG, B);
    shortconv1d_kernel<<<grid, block>>>(x, w, bias, y, T, C);
}

// round 6
// speedup vs baseline: 1.5417x; 1.5417x over previous
#include <cuda_runtime.h>
#include <cstdint>

// Causal depthwise conv1d (K=4) + SiLU, fp32.
// y[b,t,c] = silu( bias[c] + sum_k w[c,k] * x[b, t-3+k, c] )
//
// R6 (= R5 + missing include): smem tile + cp.async. Block tile = 64
// channel-quads x 32 time steps. cp.async loads the 35-row halo tile into
// smem with zero register cost, keeping occupancy high (R4 lesson: register
// buffering kills occupancy).

constexpr int C4T = 64;              // channel-quads per block (256 channels)
constexpr int TS  = 32;              // time steps per block
constexpr int NR  = TS + 3;          // smem rows (incl. 3-row causal halo)
constexpr int TPB = 256;             // 64 (c4) x 4 (time groups)
constexpr int ROWS_PER_TY = TS / 4;  // 8 outputs per thread

__device__ __forceinline__ float silu(float v) {
    return v / (1.0f + __expf(-v));
}

__device__ __forceinline__ void store_cs(float4* p, float4 v) {
    asm volatile("st.global.cs.v4.f32 [%0], {%1,%2,%3,%4};"
                 :: "l"(p), "f"(v.x), "f"(v.y), "f"(v.z), "f"(v.w) : "memory");
}

__device__ __forceinline__ void cp_async16(uint32_t smem_addr, const void* gptr) {
    asm volatile("cp.async.ca.shared.global [%0], [%1], 16;"
                 :: "r"(smem_addr), "l"(gptr) : "memory");
}

__global__ __launch_bounds__(TPB)
void shortconv1d_kernel(const float* __restrict__ x,
                        const float* __restrict__ w,
                        const float* __restrict__ bias,
                        float* __restrict__ y,
                        int T, int C) {
    __shared__ float4 tile[NR * C4T];   // 35 * 64 * 16B = 35840 B

    const int Cd4    = C >> 2;
    const int tid    = threadIdx.x;
    const int cx     = tid & (C4T - 1);     // c4 lane within tile
    const int ty     = tid >> 6;            // time group 0..3
    const int c4base = blockIdx.x * C4T;
    const int c4g    = c4base + cx;         // global c4
    const int b      = blockIdx.z;
    const int t0     = blockIdx.y * TS;

    const float4* __restrict__ x4 = reinterpret_cast<const float4*>(x);
    float4* __restrict__       y4 = reinterpret_cast<float4*>(y);

    // ---- Cooperative tile load via cp.async (rows t0-3 .. t0+TS-1) ----
    {
        const uint32_t smem_base =
            (uint32_t)__cvta_generic_to_shared(&tile[0]);
#pragma unroll
        for (int e = tid; e < NR * C4T; e += TPB) {
            const int row = e >> 6;          // e / C4T
            const int cl  = e & (C4T - 1);
            const int t   = t0 - 3 + row;
            const uint32_t dst = smem_base + (uint32_t)e * 16u;
            if (t >= 0) {
                const float4* src = &x4[((size_t)b * T + t) * Cd4 + c4base + cl];
                cp_async16(dst, src);
            } else {
                // causal zero-pad (only first time tile)
                asm volatile("st.shared.v4.b32 [%0], {%1,%1,%1,%1};"
                             :: "r"(dst), "r"(0) : "memory");
            }
        }
        asm volatile("cp.async.commit_group;" ::: "memory");
    }

    // ---- Per-channel weights + bias (L1/L2-cached broadcasts) ----
    const int c = c4g << 2;
    const float4* __restrict__ w4 = reinterpret_cast<const float4*>(w);
    const float4 wl0 = w4[c + 0];
    const float4 wl1 = w4[c + 1];
    const float4 wl2 = w4[c + 2];
    const float4 wl3 = w4[c + 3];
    const float4 bi  = reinterpret_cast<const float4*>(bias)[c4g];

    asm volatile("cp.async.wait_group 0;" ::: "memory");
    __syncthreads();

    // ---- Compute: 8 outputs per thread, sliding 3-row history from smem ----
    const int rbase = ty * ROWS_PER_TY;     // local smem row of first history
    float4 p0 = tile[(rbase + 0) * C4T + cx];
    float4 p1 = tile[(rbase + 1) * C4T + cx];
    float4 p2 = tile[(rbase + 2) * C4T + cx];

    float4* __restrict__ yp =
        &y4[((size_t)b * T + t0 + rbase) * Cd4 + c4g];
    const size_t rs = (size_t)Cd4;

#pragma unroll
    for (int r = 0; r < ROWS_PER_TY; ++r) {
        const float4 cv = tile[(rbase + 3 + r) * C4T + cx];

        float4 acc;
        acc.x = fmaf(wl0.x, p0.x, fmaf(wl0.y, p1.x, fmaf(wl0.z, p2.x, fmaf(wl0.w, cv.x, bi.x))));
        acc.y = fmaf(wl1.x, p0.y, fmaf(wl1.y, p1.y, fmaf(wl1.z, p2.y, fmaf(wl1.w, cv.y, bi.y))));
        acc.z = fmaf(wl2.x, p0.z, fmaf(wl2.y, p1.z, fmaf(wl2.z, p2.z, fmaf(wl2.w, cv.z, bi.z))));
        acc.w = fmaf(wl3.x, p0.w, fmaf(wl3.y, p1.w, fmaf(wl3.z, p2.w, fmaf(wl3.w, cv.w, bi.w))));

        float4 out;
        out.x = silu(acc.x);
        out.y = silu(acc.y);
        out.z = silu(acc.z);
        out.w = silu(acc.w);

        store_cs(yp + (size_t)r * rs, out);

        p0 = p1; p1 = p2; p2 = cv;
    }
}

extern "C" void kernel_launch(void* const* d_in, const int* in_sizes, int n_in,
                              void* d_out, int out_size) {
    const float* x    = (const float*)d_in[0];
    const float* w    = (const float*)d_in[1];
    const float* bias = (const float*)d_in[2];
    float* y          = (float*)d_out;

    const int C  = in_sizes[2];       // bias: (C,)
    const int BT = in_sizes[0] / C;   // B*T
    const int T  = 4096;
    const int B  = BT / T;

    dim3 block(TPB);
    dim3 grid((C / 4) / C4T, T / TS, B);
    shortconv1d_kernel<<<grid, block>>>(x, w, bias, y, T, C);
}